// round 12
// baseline (speedup 1.0000x reference)
#include <cuda_runtime.h>
#include <cuda_bf16.h>
#include <cstdint>

#define DIMK 32
#define NBLK 6
#define NB   16
#define NN   256
#define NITER 4

// ---------------- global scratch ----------------
__device__ float    d_fbias[NBLK * NB * DIMK];
__device__ float    d_gbias[NBLK * NB * DIMK];
// B fragments (fp16, round-to-nearest) in exact mma.sync per-lane layout:
// units: 0..39   f blk1..5:  (blk-1)*8 + kt*4 + nt          (K=32, kt 0..1)
//        40..47  g blk0:     40 + kt*4 + nt                 (K=32, h part)
//        48..127 g blk1..5:  48 + (blk-1)*16 + kt*4 + nt    (K=64, kt 0..3)
__device__ uint32_t d_bfrag[128 * 64];

// ---------------- helpers ----------------
__device__ __forceinline__ uint32_t pack_f16x2(float lo, float hi) {
    uint32_t r;
    asm("cvt.rn.f16x2.f32 %0, %1, %2;" : "=r"(r) : "f"(hi), "f"(lo));
    return r;
}
// FMA-pipe sine: exact mod-pi range reduction + odd minimax poly.
// sin(x) = (-1)^k * sin(r), r = x - k*pi, |r| <= pi/2. Max abs err ~8e-5 at edge.
__device__ __forceinline__ float sinpoly(float x) {
    float k = rintf(x * 0.318309886183790672f);
    float r = fmaf(k, -3.14159274101257324f, x);
    r = fmaf(k, 8.74227765734758577e-8f, r);
    float r2 = r * r;
    float p = fmaf(r2, -1.9515295891e-4f, 8.3321608736e-3f);
    p = fmaf(r2, p, -1.6666654611e-1f);
    p = r * fmaf(r2, p, 1.0f);
    int ki = (int)k;
    return __int_as_float(__float_as_int(p) ^ (ki << 31));
}
// static pipe selector: nt==3 group goes to the FMA pipe (25% of sins)
__device__ __forceinline__ float sin_sel(float x, int nt) {
    return (nt == 3) ? sinpoly(x) : __sinf(x);
}
#define MMA16816(d, a, b) \
    asm volatile("mma.sync.aligned.m16n8k16.row.col.f32.f16.f16.f32 " \
        "{%0,%1,%2,%3}, {%4,%5,%6,%7}, {%8,%9}, {%0,%1,%2,%3};" \
        : "+f"((d)[0]), "+f"((d)[1]), "+f"((d)[2]), "+f"((d)[3]) \
        : "r"((a)[0]), "r"((a)[1]), "r"((a)[2]), "r"((a)[3]), \
          "r"((b)[0]), "r"((b)[1]))

// chunk: load 4 B units (8 regs), run one A pass for both tiles
#define CHUNK1(ubase, A0, A1) do {                                               \
    uint32_t Bc[4][2];                                                           \
    _Pragma("unroll")                                                            \
    for (int nt = 0; nt < 4; nt++) {                                             \
        uint2 v = *(const uint2*)(s_bf + ((ubase) + nt) * 64 + lane * 2);        \
        Bc[nt][0] = v.x; Bc[nt][1] = v.y;                                        \
    }                                                                            \
    _Pragma("unroll")                                                            \
    for (int nt = 0; nt < 4; nt++) {                                             \
        MMA16816(acc[0][nt], (A0), Bc[nt]);                                      \
        MMA16816(acc[1][nt], (A1), Bc[nt]);                                      \
    }                                                                            \
} while (0)

// ---------------- precompute kernel (parallelized: 48 blocks) ----------------
// blocks 0..15  : per-batch fused biases (b = blockIdx.x)
// blocks 16..47 : B-fragment conversion (256 entries per block)
__global__ void precompute_kernel(
    const float* __restrict__ x_params, const float* __restrict__ t_params,
    const float* __restrict__ xW1, const float* __restrict__ xb1,
    const float* __restrict__ xW2, const float* __restrict__ xb2,
    const float* __restrict__ tW1, const float* __restrict__ tb1,
    const float* __restrict__ tW2, const float* __restrict__ tb2,
    const float* __restrict__ h0,  const float* __restrict__ gh0,
    const float* __restrict__ f_Wh, const float* __restrict__ f_bh,
    const float* __restrict__ f_Wz, const float* __restrict__ f_bz,
    const float* __restrict__ g_Wh, const float* __restrict__ g_bh,
    const float* __restrict__ g_Wz, const float* __restrict__ g_bz)
{
    const int t = threadIdx.x;  // 256 threads
    if (blockIdx.x < 16) {
        const int b = blockIdx.x;
        __shared__ float s1x[DIMK], s1t[DIMK], ex[DIMK], et[DIMK];
        if (t < DIMK) {
            float a = xb1[t];
            for (int p = 0; p < 16; p++) a += x_params[b * 16 + p] * xW1[p * DIMK + t];
            s1x[t] = sinf(a);
            float c = tb1[t];
            for (int p = 0; p < 8; p++) c += t_params[b * 8 + p] * tW1[p * DIMK + t];
            s1t[t] = sinf(c);
        }
        __syncthreads();
        if (t < DIMK) {
            float a = xb2[t], c = tb2[t];
            for (int m = 0; m < DIMK; m++) {
                a += s1x[m] * xW2[m * DIMK + t];
                c += s1t[m] * tW2[m * DIMK + t];
            }
            ex[t] = a;
            et[t] = c;
        }
        __syncthreads();
        if (t < NBLK * DIMK) {
            int blk = t >> 5, k = t & 31;
            float fa = f_bh[blk * DIMK + k] + f_bz[blk * DIMK + k];
            for (int m = 0; m < DIMK; m++)
                fa += et[m] * f_Wz[(blk * 34 + 2 + m) * DIMK + k];
            if (blk == 0)
                for (int m = 0; m < DIMK; m++)
                    fa += h0[m] * f_Wh[m * DIMK + k];
            d_fbias[(blk * NB + b) * DIMK + k] = fa;
            float ga = g_bh[blk * DIMK + k] + g_bz[blk * DIMK + k];
            for (int m = 0; m < DIMK; m++)
                ga += ex[m] * g_Wz[(blk * 64 + 32 + m) * DIMK + k];
            if (blk == 0)
                for (int m = 0; m < DIMK; m++)
                    ga += gh0[m] * g_Wh[m * DIMK + k];
            d_gbias[(blk * NB + b) * DIMK + k] = ga;
        }
    } else {
        // ---- B fragments (fp16 RN, per-lane mma layout) ----
        int e = (blockIdx.x - 16) * 256 + t;   // 32 * 256 = 8192 entries
        int u = e >> 6, r6 = e & 63, lane = r6 >> 1, reg = r6 & 1;
        int kt, nt, blk, isG;
        if (u < 40)      { blk = u / 8 + 1; int q = u % 8;  kt = q >> 2; nt = q & 3; isG = 0; }
        else if (u < 48) { int q = u - 40;  blk = 0;        kt = q >> 2; nt = q & 3; isG = 1; }
        else             { int q = u - 48;  blk = q / 16 + 1; q %= 16;   kt = q >> 2; nt = q & 3; isG = 1; }
        int k0 = kt * 16 + (lane & 3) * 2 + reg * 8;  // rows k0, k0+1
        int n  = nt * 8 + (lane >> 2);
        float w0, w1;
        if (!isG) {
            w0 = f_Wh[blk * 1024 + k0 * 32 + n];
            w1 = f_Wh[blk * 1024 + (k0 + 1) * 32 + n];
        } else if (blk == 0) {
            w0 = g_Wz[k0 * 32 + n];          // g blk0: h part rows 0..31
            w1 = g_Wz[(k0 + 1) * 32 + n];
        } else {
            w0 = (k0 < 32)     ? g_Wh[blk * 1024 + k0 * 32 + n]
                               : g_Wz[blk * 2048 + (k0 - 32) * 32 + n];
            int k1 = k0 + 1;
            w1 = (k1 < 32)     ? g_Wh[blk * 1024 + k1 * 32 + n]
                               : g_Wz[blk * 2048 + (k1 - 32) * 32 + n];
        }
        d_bfrag[e] = pack_f16x2(w0, w1);   // low half = smaller k
    }
}

// ---------------- smem layout ----------------
#define SM_BF_U32 (128 * 64)                      // 8192 u32 = 32 KB
#define SMEM_BYTES (32768 + (192 * 4 + 64) * 4)

// ---------- main kernel: 128 thr, tt=2 (B-sharing), 6 CTAs/SM, hybrid sin ----------
__global__ void __launch_bounds__(128, 6) main_kernel(
    const float* __restrict__ coords,  // (B,N,2)
    const float* __restrict__ f_Wz,    // (6,34,32)
    const float* __restrict__ d_W,     // (32)
    const float* __restrict__ d_b,     // (1)
    float* __restrict__ out)           // (B,N,N)
{
    extern __shared__ char smem[];
    uint32_t* s_bf  = (uint32_t*)smem;
    float*    s_fb  = (float*)(smem + 32768);
    float*    s_z0  = s_fb + 192;
    float*    s_z1  = s_z0 + 192;
    float*    s_gb  = s_z1 + 192;
    float*    s_dW  = s_gb + 192;   // 32

    const int tid  = threadIdx.x;
    const int w    = tid >> 5;
    const int lane = tid & 31;
    const int t4   = lane >> 2;
    const int m4   = lane & 3;
    // grid: [b(4b) | igrp(6b) | jgrp(1b)] = 2048 CTAs
    const int b    = blockIdx.x >> 7;
    const int igrp = (blockIdx.x >> 1) & 63;
    const int jgrp = blockIdx.x & 1;
    const int i0   = igrp * NITER;

    // ---- stage B fragments + per-batch vectors ----
    {
        const uint4* src = (const uint4*)d_bfrag;
        uint4* dst = (uint4*)s_bf;
        for (int idx = tid; idx < SM_BF_U32 / 4; idx += 128) dst[idx] = src[idx];
    }
    for (int idx = tid; idx < 192; idx += 128) {
        int blk = idx >> 5, k = idx & 31;
        s_fb[idx] = d_fbias[(blk * NB + b) * DIMK + k];
        s_gb[idx] = d_gbias[(blk * NB + b) * DIMK + k];
        s_z0[idx] = f_Wz[(blk * 34 + 0) * DIMK + k];
        s_z1[idx] = f_Wz[(blk * 34 + 1) * DIMK + k];
    }
    if (tid < 32) s_dW[tid] = d_W[tid];
    __syncthreads();

    const float dbv = d_b[0];

    // x for this warp's two tiles (j fixed across i)
    float xr[2][2];
#pragma unroll
    for (int tt = 0; tt < 2; tt++) {
        int j = jgrp * 128 + (w * 2 + tt) * 16 + t4;
        xr[tt][0] = coords[(b * NN + j) * 2 + 0];
        xr[tt][1] = coords[(b * NN + j + 8) * 2 + 0];
    }

    uint32_t ahi[2][8], hh[2][8];
    float acc[2][4][4];

#pragma unroll 1
    for (int ii = 0; ii < NITER; ii++) {
        const int i = i0 + ii;
        const float tc = coords[(b * NN + i) * 2 + 1];

        // ========== f blk0: h = sin(fb + tc*z1 + x*z0) ==========
#pragma unroll
        for (int tt = 0; tt < 2; tt++)
#pragma unroll
            for (int nt = 0; nt < 4; nt++) {
                int c = nt * 8 + m4 * 2;
                float2 fb2 = *(float2*)(s_fb + c);
                float2 z02 = *(float2*)(s_z0 + c);
                float2 z12 = *(float2*)(s_z1 + c);
                float bx = fmaf(tc, z12.x, fb2.x);
                float by = fmaf(tc, z12.y, fb2.y);
                float s0 = sin_sel(fmaf(xr[tt][0], z02.x, bx), nt);
                float s1 = sin_sel(fmaf(xr[tt][0], z02.y, by), nt);
                float s2 = sin_sel(fmaf(xr[tt][1], z02.x, bx), nt);
                float s3 = sin_sel(fmaf(xr[tt][1], z02.y, by), nt);
                int kt = nt >> 1, sl = (nt & 1) * 2;
                ahi[tt][kt * 4 + sl]     = pack_f16x2(s0, s1);
                ahi[tt][kt * 4 + sl + 1] = pack_f16x2(s2, s3);
            }

        // ========== f blks 1..5 (K=32, 1-pass) ==========
#pragma unroll 1
        for (int blk = 1; blk < NBLK; blk++) {
            const int ub = (blk - 1) * 8;
            const bool lastf = (blk == NBLK - 1);
#pragma unroll
            for (int tt = 0; tt < 2; tt++)
#pragma unroll
                for (int nt = 0; nt < 4; nt++) {
                    int c = blk * 32 + nt * 8 + m4 * 2;
                    float2 fb2 = *(float2*)(s_fb + c);
                    float2 z02 = *(float2*)(s_z0 + c);
                    float2 z12 = *(float2*)(s_z1 + c);
                    float bx = fmaf(tc, z12.x, fb2.x);
                    float by = fmaf(tc, z12.y, fb2.y);
                    acc[tt][nt][0] = fmaf(xr[tt][0], z02.x, bx);
                    acc[tt][nt][1] = fmaf(xr[tt][0], z02.y, by);
                    acc[tt][nt][2] = fmaf(xr[tt][1], z02.x, bx);
                    acc[tt][nt][3] = fmaf(xr[tt][1], z02.y, by);
                }
#pragma unroll
            for (int kt = 0; kt < 2; kt++)
                CHUNK1(ub + kt * 4, &ahi[0][kt * 4], &ahi[1][kt * 4]);
            // epilogue: sin + repack (f output h goes to hh)
#pragma unroll
            for (int tt = 0; tt < 2; tt++)
#pragma unroll
                for (int nt = 0; nt < 4; nt++) {
                    float s0 = sin_sel(acc[tt][nt][0], nt);
                    float s1 = sin_sel(acc[tt][nt][1], nt);
                    float s2 = sin_sel(acc[tt][nt][2], nt);
                    float s3 = sin_sel(acc[tt][nt][3], nt);
                    int kt = nt >> 1, sl = (nt & 1) * 2;
                    uint32_t p01 = pack_f16x2(s0, s1);
                    uint32_t p23 = pack_f16x2(s2, s3);
                    if (!lastf) {
                        ahi[tt][kt * 4 + sl]     = p01;
                        ahi[tt][kt * 4 + sl + 1] = p23;
                    } else {
                        hh[tt][kt * 4 + sl]     = p01;
                        hh[tt][kt * 4 + sl + 1] = p23;
                    }
                }
        }

        // ========== g blk0 (K=32, A = h) ==========
        {
#pragma unroll
            for (int tt = 0; tt < 2; tt++)
#pragma unroll
                for (int nt = 0; nt < 4; nt++) {
                    int c = nt * 8 + m4 * 2;
                    float2 gb2 = *(float2*)(s_gb + c);
                    acc[tt][nt][0] = gb2.x;
                    acc[tt][nt][1] = gb2.y;
                    acc[tt][nt][2] = gb2.x;
                    acc[tt][nt][3] = gb2.y;
                }
#pragma unroll
            for (int kt = 0; kt < 2; kt++)
                CHUNK1(40 + kt * 4, &hh[0][kt * 4], &hh[1][kt * 4]);
#pragma unroll
            for (int tt = 0; tt < 2; tt++)
#pragma unroll
                for (int nt = 0; nt < 4; nt++) {
                    float s0 = sin_sel(acc[tt][nt][0], nt);
                    float s1 = sin_sel(acc[tt][nt][1], nt);
                    float s2 = sin_sel(acc[tt][nt][2], nt);
                    float s3 = sin_sel(acc[tt][nt][3], nt);
                    int kt = nt >> 1, sl = (nt & 1) * 2;
                    ahi[tt][kt * 4 + sl]     = pack_f16x2(s0, s1);
                    ahi[tt][kt * 4 + sl + 1] = pack_f16x2(s2, s3);
                }
        }

        // ========== g blks 1..5 (K=64: A = [gh ; h], both 1-pass) ==========
        float p0[2], p1[2];
#pragma unroll
        for (int tt = 0; tt < 2; tt++) { p0[tt] = 0.0f; p1[tt] = 0.0f; }

#pragma unroll 1
        for (int blk = 1; blk < NBLK; blk++) {
            const int ub = 48 + (blk - 1) * 16;
#pragma unroll
            for (int tt = 0; tt < 2; tt++)
#pragma unroll
                for (int nt = 0; nt < 4; nt++) {
                    int c = blk * 32 + nt * 8 + m4 * 2;
                    float2 gb2 = *(float2*)(s_gb + c);
                    acc[tt][nt][0] = gb2.x;
                    acc[tt][nt][1] = gb2.y;
                    acc[tt][nt][2] = gb2.x;
                    acc[tt][nt][3] = gb2.y;
                }
            // kt 0,1: gh part; kt 2,3 (ub+8..): h part
#pragma unroll
            for (int kt = 0; kt < 2; kt++)
                CHUNK1(ub + kt * 4, &ahi[0][kt * 4], &ahi[1][kt * 4]);
#pragma unroll
            for (int kt = 0; kt < 2; kt++)
                CHUNK1(ub + 8 + kt * 4, &hh[0][kt * 4], &hh[1][kt * 4]);

            const bool last = (blk == NBLK - 1);
#pragma unroll
            for (int tt = 0; tt < 2; tt++)
#pragma unroll
                for (int nt = 0; nt < 4; nt++) {
                    float s0 = sin_sel(acc[tt][nt][0], nt);
                    float s1 = sin_sel(acc[tt][nt][1], nt);
                    float s2 = sin_sel(acc[tt][nt][2], nt);
                    float s3 = sin_sel(acc[tt][nt][3], nt);
                    if (!last) {
                        int kt = nt >> 1, sl = (nt & 1) * 2;
                        ahi[tt][kt * 4 + sl]     = pack_f16x2(s0, s1);
                        ahi[tt][kt * 4 + sl + 1] = pack_f16x2(s2, s3);
                    } else {
                        int c = nt * 8 + m4 * 2;
                        float2 dw2 = *(float2*)(s_dW + c);
                        p0[tt] += s0 * dw2.x + s1 * dw2.y;
                        p1[tt] += s2 * dw2.x + s3 * dw2.y;
                    }
                }
        }

        // ========== decode reduce + store ==========
#pragma unroll
        for (int tt = 0; tt < 2; tt++) {
            p0[tt] += __shfl_xor_sync(0xffffffffu, p0[tt], 1);
            p0[tt] += __shfl_xor_sync(0xffffffffu, p0[tt], 2);
            p1[tt] += __shfl_xor_sync(0xffffffffu, p1[tt], 1);
            p1[tt] += __shfl_xor_sync(0xffffffffu, p1[tt], 2);
            if (m4 == 0) {
                int r0 = jgrp * 128 + (w * 2 + tt) * 16 + t4;
                out[b * (NN * NN) + i * NN + r0]     = p0[tt] + dbv;
                out[b * (NN * NN) + i * NN + r0 + 8] = p1[tt] + dbv;
            }
        }
    }
}

// ---------------- launch ----------------
extern "C" void kernel_launch(void* const* d_in, const int* in_sizes, int n_in,
                              void* d_out, int out_size) {
    const float* coords   = (const float*)d_in[0];
    const float* x_params = (const float*)d_in[1];
    const float* t_params = (const float*)d_in[2];
    const float* xW1 = (const float*)d_in[3];
    const float* xb1 = (const float*)d_in[4];
    const float* xW2 = (const float*)d_in[5];
    const float* xb2 = (const float*)d_in[6];
    const float* tW1 = (const float*)d_in[7];
    const float* tb1 = (const float*)d_in[8];
    const float* tW2 = (const float*)d_in[9];
    const float* tb2 = (const float*)d_in[10];
    const float* h0  = (const float*)d_in[11];
    const float* gh0 = (const float*)d_in[12];
    const float* f_Wh = (const float*)d_in[13];
    const float* f_bh = (const float*)d_in[14];
    const float* f_Wz = (const float*)d_in[15];
    const float* f_bz = (const float*)d_in[16];
    const float* g_Wh = (const float*)d_in[17];
    const float* g_bh = (const float*)d_in[18];
    const float* g_Wz = (const float*)d_in[19];
    const float* g_bz = (const float*)d_in[20];
    const float* d_W  = (const float*)d_in[21];
    const float* d_b  = (const float*)d_in[22];
    float* out = (float*)d_out;

    precompute_kernel<<<48, 256>>>(x_params, t_params, xW1, xb1, xW2, xb2,
                                   tW1, tb1, tW2, tb2, h0, gh0,
                                   f_Wh, f_bh, f_Wz, f_bz,
                                   g_Wh, g_bh, g_Wz, g_bz);

    cudaFuncSetAttribute(main_kernel, cudaFuncAttributeMaxDynamicSharedMemorySize,
                         SMEM_BYTES);
    // grid: [b(4b) | igrp(6b) | jgrp(1b)] = 16 * 64 * 2 = 2048 CTAs
    main_kernel<<<NB * (NN / NITER) * 2, 128, SMEM_BYTES>>>(coords, f_Wz, d_W, d_b, out);
}

// round 13
// speedup vs baseline: 1.2414x; 1.2414x over previous
#include <cuda_runtime.h>
#include <cuda_bf16.h>
#include <cstdint>

#define DIMK 32
#define NBLK 6
#define NB   16
#define NN   256
#define NITER 4

// ---------------- global scratch ----------------
__device__ float    d_fbias[NBLK * NB * DIMK];
__device__ float    d_gbias[NBLK * NB * DIMK];
// B fragments (fp16, round-to-nearest) in exact mma.sync per-lane layout:
// units: 0..39   f blk1..5:  (blk-1)*8 + kt*4 + nt          (K=32, kt 0..1)
//        40..47  g blk0:     40 + kt*4 + nt                 (K=32, h part)
//        48..127 g blk1..5:  48 + (blk-1)*16 + kt*4 + nt    (K=64, kt 0..3)
__device__ uint32_t d_bfrag[128 * 64];

// ---------------- helpers ----------------
__device__ __forceinline__ uint32_t pack_f16x2(float lo, float hi) {
    uint32_t r;
    asm("cvt.rn.f16x2.f32 %0, %1, %2;" : "=r"(r) : "f"(hi), "f"(lo));
    return r;
}
#define MMA16816(d, a, b) \
    asm volatile("mma.sync.aligned.m16n8k16.row.col.f32.f16.f16.f32 " \
        "{%0,%1,%2,%3}, {%4,%5,%6,%7}, {%8,%9}, {%0,%1,%2,%3};" \
        : "+f"((d)[0]), "+f"((d)[1]), "+f"((d)[2]), "+f"((d)[3]) \
        : "r"((a)[0]), "r"((a)[1]), "r"((a)[2]), "r"((a)[3]), \
          "r"((b)[0]), "r"((b)[1]))

// chunk: load 4 B units (8 regs), run one A pass for both tiles
#define CHUNK1(ubase, A0, A1) do {                                               \
    uint32_t Bc[4][2];                                                           \
    _Pragma("unroll")                                                            \
    for (int nt = 0; nt < 4; nt++) {                                             \
        uint2 v = *(const uint2*)(s_bf + ((ubase) + nt) * 64 + lane * 2);        \
        Bc[nt][0] = v.x; Bc[nt][1] = v.y;                                        \
    }                                                                            \
    _Pragma("unroll")                                                            \
    for (int nt = 0; nt < 4; nt++) {                                             \
        MMA16816(acc[0][nt], (A0), Bc[nt]);                                      \
        MMA16816(acc[1][nt], (A1), Bc[nt]);                                      \
    }                                                                            \
} while (0)

// ---------------- precompute kernel (parallelized: 48 blocks) ----------------
// blocks 0..15  : per-batch fused biases (b = blockIdx.x)
// blocks 16..47 : B-fragment conversion (256 entries per block)
__global__ void precompute_kernel(
    const float* __restrict__ x_params, const float* __restrict__ t_params,
    const float* __restrict__ xW1, const float* __restrict__ xb1,
    const float* __restrict__ xW2, const float* __restrict__ xb2,
    const float* __restrict__ tW1, const float* __restrict__ tb1,
    const float* __restrict__ tW2, const float* __restrict__ tb2,
    const float* __restrict__ h0,  const float* __restrict__ gh0,
    const float* __restrict__ f_Wh, const float* __restrict__ f_bh,
    const float* __restrict__ f_Wz, const float* __restrict__ f_bz,
    const float* __restrict__ g_Wh, const float* __restrict__ g_bh,
    const float* __restrict__ g_Wz, const float* __restrict__ g_bz)
{
    const int t = threadIdx.x;  // 256 threads
    if (blockIdx.x < 16) {
        const int b = blockIdx.x;
        __shared__ float s1x[DIMK], s1t[DIMK], ex[DIMK], et[DIMK];
        if (t < DIMK) {
            float a = xb1[t];
            for (int p = 0; p < 16; p++) a += x_params[b * 16 + p] * xW1[p * DIMK + t];
            s1x[t] = sinf(a);
            float c = tb1[t];
            for (int p = 0; p < 8; p++) c += t_params[b * 8 + p] * tW1[p * DIMK + t];
            s1t[t] = sinf(c);
        }
        __syncthreads();
        if (t < DIMK) {
            float a = xb2[t], c = tb2[t];
            for (int m = 0; m < DIMK; m++) {
                a += s1x[m] * xW2[m * DIMK + t];
                c += s1t[m] * tW2[m * DIMK + t];
            }
            ex[t] = a;
            et[t] = c;
        }
        __syncthreads();
        if (t < NBLK * DIMK) {
            int blk = t >> 5, k = t & 31;
            float fa = f_bh[blk * DIMK + k] + f_bz[blk * DIMK + k];
            for (int m = 0; m < DIMK; m++)
                fa += et[m] * f_Wz[(blk * 34 + 2 + m) * DIMK + k];
            if (blk == 0)
                for (int m = 0; m < DIMK; m++)
                    fa += h0[m] * f_Wh[m * DIMK + k];
            d_fbias[(blk * NB + b) * DIMK + k] = fa;
            float ga = g_bh[blk * DIMK + k] + g_bz[blk * DIMK + k];
            for (int m = 0; m < DIMK; m++)
                ga += ex[m] * g_Wz[(blk * 64 + 32 + m) * DIMK + k];
            if (blk == 0)
                for (int m = 0; m < DIMK; m++)
                    ga += gh0[m] * g_Wh[m * DIMK + k];
            d_gbias[(blk * NB + b) * DIMK + k] = ga;
        }
    } else {
        // ---- B fragments (fp16 RN, per-lane mma layout) ----
        int e = (blockIdx.x - 16) * 256 + t;   // 32 * 256 = 8192 entries
        int u = e >> 6, r6 = e & 63, lane = r6 >> 1, reg = r6 & 1;
        int kt, nt, blk, isG;
        if (u < 40)      { blk = u / 8 + 1; int q = u % 8;  kt = q >> 2; nt = q & 3; isG = 0; }
        else if (u < 48) { int q = u - 40;  blk = 0;        kt = q >> 2; nt = q & 3; isG = 1; }
        else             { int q = u - 48;  blk = q / 16 + 1; q %= 16;   kt = q >> 2; nt = q & 3; isG = 1; }
        int k0 = kt * 16 + (lane & 3) * 2 + reg * 8;  // rows k0, k0+1
        int n  = nt * 8 + (lane >> 2);
        float w0, w1;
        if (!isG) {
            w0 = f_Wh[blk * 1024 + k0 * 32 + n];
            w1 = f_Wh[blk * 1024 + (k0 + 1) * 32 + n];
        } else if (blk == 0) {
            w0 = g_Wz[k0 * 32 + n];          // g blk0: h part rows 0..31
            w1 = g_Wz[(k0 + 1) * 32 + n];
        } else {
            w0 = (k0 < 32)     ? g_Wh[blk * 1024 + k0 * 32 + n]
                               : g_Wz[blk * 2048 + (k0 - 32) * 32 + n];
            int k1 = k0 + 1;
            w1 = (k1 < 32)     ? g_Wh[blk * 1024 + k1 * 32 + n]
                               : g_Wz[blk * 2048 + (k1 - 32) * 32 + n];
        }
        d_bfrag[e] = pack_f16x2(w0, w1);   // low half = smaller k
    }
}

// ---------------- smem layout ----------------
#define SM_BF_U32 (128 * 64)                      // 8192 u32 = 32 KB
#define SMEM_BYTES (32768 + (192 * 4 + 64) * 4)

// ---------- main kernel: 128 thr, tt=2 (B-sharing), 5 CTAs/SM, all-1-pass ----------
__global__ void __launch_bounds__(128, 5) main_kernel(
    const float* __restrict__ coords,  // (B,N,2)
    const float* __restrict__ f_Wz,    // (6,34,32)
    const float* __restrict__ d_W,     // (32)
    const float* __restrict__ d_b,     // (1)
    float* __restrict__ out)           // (B,N,N)
{
    extern __shared__ char smem[];
    uint32_t* s_bf  = (uint32_t*)smem;
    float*    s_fb  = (float*)(smem + 32768);
    float*    s_z0  = s_fb + 192;
    float*    s_z1  = s_z0 + 192;
    float*    s_gb  = s_z1 + 192;
    float*    s_dW  = s_gb + 192;   // 32

    const int tid  = threadIdx.x;
    const int w    = tid >> 5;
    const int lane = tid & 31;
    const int t4   = lane >> 2;
    const int m4   = lane & 3;
    // grid: [b(4b) | igrp(6b) | jgrp(1b)] = 2048 CTAs
    const int b    = blockIdx.x >> 7;
    const int igrp = (blockIdx.x >> 1) & 63;
    const int jgrp = blockIdx.x & 1;
    const int i0   = igrp * NITER;

    // ---- stage B fragments + per-batch vectors ----
    {
        const uint4* src = (const uint4*)d_bfrag;
        uint4* dst = (uint4*)s_bf;
        for (int idx = tid; idx < SM_BF_U32 / 4; idx += 128) dst[idx] = src[idx];
    }
    for (int idx = tid; idx < 192; idx += 128) {
        int blk = idx >> 5, k = idx & 31;
        s_fb[idx] = d_fbias[(blk * NB + b) * DIMK + k];
        s_gb[idx] = d_gbias[(blk * NB + b) * DIMK + k];
        s_z0[idx] = f_Wz[(blk * 34 + 0) * DIMK + k];
        s_z1[idx] = f_Wz[(blk * 34 + 1) * DIMK + k];
    }
    if (tid < 32) s_dW[tid] = d_W[tid];
    __syncthreads();

    const float dbv = d_b[0];

    // x for this warp's two tiles (j fixed across i)
    float xr[2][2];
#pragma unroll
    for (int tt = 0; tt < 2; tt++) {
        int j = jgrp * 128 + (w * 2 + tt) * 16 + t4;
        xr[tt][0] = coords[(b * NN + j) * 2 + 0];
        xr[tt][1] = coords[(b * NN + j + 8) * 2 + 0];
    }

    uint32_t ahi[2][8], hh[2][8];
    float acc[2][4][4];

#pragma unroll 1
    for (int ii = 0; ii < NITER; ii++) {
        const int i = i0 + ii;
        const float tc = coords[(b * NN + i) * 2 + 1];

        // ========== f blk0: h = sin(fb + tc*z1 + x*z0) ==========
#pragma unroll
        for (int tt = 0; tt < 2; tt++)
#pragma unroll
            for (int nt = 0; nt < 4; nt++) {
                int c = nt * 8 + m4 * 2;
                float2 fb2 = *(float2*)(s_fb + c);
                float2 z02 = *(float2*)(s_z0 + c);
                float2 z12 = *(float2*)(s_z1 + c);
                float bx = fmaf(tc, z12.x, fb2.x);
                float by = fmaf(tc, z12.y, fb2.y);
                float s0 = __sinf(fmaf(xr[tt][0], z02.x, bx));
                float s1 = __sinf(fmaf(xr[tt][0], z02.y, by));
                float s2 = __sinf(fmaf(xr[tt][1], z02.x, bx));
                float s3 = __sinf(fmaf(xr[tt][1], z02.y, by));
                int kt = nt >> 1, sl = (nt & 1) * 2;
                ahi[tt][kt * 4 + sl]     = pack_f16x2(s0, s1);
                ahi[tt][kt * 4 + sl + 1] = pack_f16x2(s2, s3);
            }

        // ========== f blks 1..5 (K=32, 1-pass) ==========
#pragma unroll 1
        for (int blk = 1; blk < NBLK; blk++) {
            const int ub = (blk - 1) * 8;
            const bool lastf = (blk == NBLK - 1);
#pragma unroll
            for (int tt = 0; tt < 2; tt++)
#pragma unroll
                for (int nt = 0; nt < 4; nt++) {
                    int c = blk * 32 + nt * 8 + m4 * 2;
                    float2 fb2 = *(float2*)(s_fb + c);
                    float2 z02 = *(float2*)(s_z0 + c);
                    float2 z12 = *(float2*)(s_z1 + c);
                    float bx = fmaf(tc, z12.x, fb2.x);
                    float by = fmaf(tc, z12.y, fb2.y);
                    acc[tt][nt][0] = fmaf(xr[tt][0], z02.x, bx);
                    acc[tt][nt][1] = fmaf(xr[tt][0], z02.y, by);
                    acc[tt][nt][2] = fmaf(xr[tt][1], z02.x, bx);
                    acc[tt][nt][3] = fmaf(xr[tt][1], z02.y, by);
                }
#pragma unroll
            for (int kt = 0; kt < 2; kt++)
                CHUNK1(ub + kt * 4, &ahi[0][kt * 4], &ahi[1][kt * 4]);
            // epilogue: sin + repack (f output h goes to hh)
#pragma unroll
            for (int tt = 0; tt < 2; tt++)
#pragma unroll
                for (int nt = 0; nt < 4; nt++) {
                    float s0 = __sinf(acc[tt][nt][0]);
                    float s1 = __sinf(acc[tt][nt][1]);
                    float s2 = __sinf(acc[tt][nt][2]);
                    float s3 = __sinf(acc[tt][nt][3]);
                    int kt = nt >> 1, sl = (nt & 1) * 2;
                    uint32_t p01 = pack_f16x2(s0, s1);
                    uint32_t p23 = pack_f16x2(s2, s3);
                    if (!lastf) {
                        ahi[tt][kt * 4 + sl]     = p01;
                        ahi[tt][kt * 4 + sl + 1] = p23;
                    } else {
                        hh[tt][kt * 4 + sl]     = p01;
                        hh[tt][kt * 4 + sl + 1] = p23;
                    }
                }
        }

        // ========== g blk0 (K=32, A = h) ==========
        {
#pragma unroll
            for (int tt = 0; tt < 2; tt++)
#pragma unroll
                for (int nt = 0; nt < 4; nt++) {
                    int c = nt * 8 + m4 * 2;
                    float2 gb2 = *(float2*)(s_gb + c);
                    acc[tt][nt][0] = gb2.x;
                    acc[tt][nt][1] = gb2.y;
                    acc[tt][nt][2] = gb2.x;
                    acc[tt][nt][3] = gb2.y;
                }
#pragma unroll
            for (int kt = 0; kt < 2; kt++)
                CHUNK1(40 + kt * 4, &hh[0][kt * 4], &hh[1][kt * 4]);
#pragma unroll
            for (int tt = 0; tt < 2; tt++)
#pragma unroll
                for (int nt = 0; nt < 4; nt++) {
                    float s0 = __sinf(acc[tt][nt][0]);
                    float s1 = __sinf(acc[tt][nt][1]);
                    float s2 = __sinf(acc[tt][nt][2]);
                    float s3 = __sinf(acc[tt][nt][3]);
                    int kt = nt >> 1, sl = (nt & 1) * 2;
                    ahi[tt][kt * 4 + sl]     = pack_f16x2(s0, s1);
                    ahi[tt][kt * 4 + sl + 1] = pack_f16x2(s2, s3);
                }
        }

        // ========== g blks 1..5 (K=64: A = [gh ; h], both 1-pass) ==========
        float p0[2], p1[2];
#pragma unroll
        for (int tt = 0; tt < 2; tt++) { p0[tt] = 0.0f; p1[tt] = 0.0f; }

#pragma unroll 1
        for (int blk = 1; blk < NBLK; blk++) {
            const int ub = 48 + (blk - 1) * 16;
#pragma unroll
            for (int tt = 0; tt < 2; tt++)
#pragma unroll
                for (int nt = 0; nt < 4; nt++) {
                    int c = blk * 32 + nt * 8 + m4 * 2;
                    float2 gb2 = *(float2*)(s_gb + c);
                    acc[tt][nt][0] = gb2.x;
                    acc[tt][nt][1] = gb2.y;
                    acc[tt][nt][2] = gb2.x;
                    acc[tt][nt][3] = gb2.y;
                }
            // kt 0,1: gh part; kt 2,3 (ub+8..): h part
#pragma unroll
            for (int kt = 0; kt < 2; kt++)
                CHUNK1(ub + kt * 4, &ahi[0][kt * 4], &ahi[1][kt * 4]);
#pragma unroll
            for (int kt = 0; kt < 2; kt++)
                CHUNK1(ub + 8 + kt * 4, &hh[0][kt * 4], &hh[1][kt * 4]);

            const bool last = (blk == NBLK - 1);
#pragma unroll
            for (int tt = 0; tt < 2; tt++)
#pragma unroll
                for (int nt = 0; nt < 4; nt++) {
                    float s0 = __sinf(acc[tt][nt][0]);
                    float s1 = __sinf(acc[tt][nt][1]);
                    float s2 = __sinf(acc[tt][nt][2]);
                    float s3 = __sinf(acc[tt][nt][3]);
                    if (!last) {
                        int kt = nt >> 1, sl = (nt & 1) * 2;
                        ahi[tt][kt * 4 + sl]     = pack_f16x2(s0, s1);
                        ahi[tt][kt * 4 + sl + 1] = pack_f16x2(s2, s3);
                    } else {
                        int c = nt * 8 + m4 * 2;
                        float2 dw2 = *(float2*)(s_dW + c);
                        p0[tt] += s0 * dw2.x + s1 * dw2.y;
                        p1[tt] += s2 * dw2.x + s3 * dw2.y;
                    }
                }
        }

        // ========== decode reduce + store ==========
#pragma unroll
        for (int tt = 0; tt < 2; tt++) {
            p0[tt] += __shfl_xor_sync(0xffffffffu, p0[tt], 1);
            p0[tt] += __shfl_xor_sync(0xffffffffu, p0[tt], 2);
            p1[tt] += __shfl_xor_sync(0xffffffffu, p1[tt], 1);
            p1[tt] += __shfl_xor_sync(0xffffffffu, p1[tt], 2);
            if (m4 == 0) {
                int r0 = jgrp * 128 + (w * 2 + tt) * 16 + t4;
                out[b * (NN * NN) + i * NN + r0]     = p0[tt] + dbv;
                out[b * (NN * NN) + i * NN + r0 + 8] = p1[tt] + dbv;
            }
        }
    }
}

// ---------------- launch ----------------
extern "C" void kernel_launch(void* const* d_in, const int* in_sizes, int n_in,
                              void* d_out, int out_size) {
    const float* coords   = (const float*)d_in[0];
    const float* x_params = (const float*)d_in[1];
    const float* t_params = (const float*)d_in[2];
    const float* xW1 = (const float*)d_in[3];
    const float* xb1 = (const float*)d_in[4];
    const float* xW2 = (const float*)d_in[5];
    const float* xb2 = (const float*)d_in[6];
    const float* tW1 = (const float*)d_in[7];
    const float* tb1 = (const float*)d_in[8];
    const float* tW2 = (const float*)d_in[9];
    const float* tb2 = (const float*)d_in[10];
    const float* h0  = (const float*)d_in[11];
    const float* gh0 = (const float*)d_in[12];
    const float* f_Wh = (const float*)d_in[13];
    const float* f_bh = (const float*)d_in[14];
    const float* f_Wz = (const float*)d_in[15];
    const float* f_bz = (const float*)d_in[16];
    const float* g_Wh = (const float*)d_in[17];
    const float* g_bh = (const float*)d_in[18];
    const float* g_Wz = (const float*)d_in[19];
    const float* g_bz = (const float*)d_in[20];
    const float* d_W  = (const float*)d_in[21];
    const float* d_b  = (const float*)d_in[22];
    float* out = (float*)d_out;

    precompute_kernel<<<48, 256>>>(x_params, t_params, xW1, xb1, xW2, xb2,
                                   tW1, tb1, tW2, tb2, h0, gh0,
                                   f_Wh, f_bh, f_Wz, f_bz,
                                   g_Wh, g_bh, g_Wz, g_bz);

    cudaFuncSetAttribute(main_kernel, cudaFuncAttributeMaxDynamicSharedMemorySize,
                         SMEM_BYTES);
    // grid: [b(4b) | igrp(6b) | jgrp(1b)] = 16 * 64 * 2 = 2048 CTAs
    main_kernel<<<NB * (NN / NITER) * 2, 128, SMEM_BYTES>>>(coords, f_Wz, d_W, d_b, out);
}

// round 14
// speedup vs baseline: 1.2448x; 1.0027x over previous
#include <cuda_runtime.h>
#include <cuda_bf16.h>
#include <cstdint>

#define DIMK 32
#define NBLK 6
#define NB   16
#define NN   256
#define NITER 4

// ---------------- global scratch ----------------
__device__ float    d_fbias[NBLK * NB * DIMK];
__device__ float    d_gbias[NBLK * NB * DIMK];
// B fragments (fp16, round-to-nearest) in exact mma.sync per-lane layout:
// units: 0..39   f blk1..5:  (blk-1)*8 + kt*4 + nt          (K=32, kt 0..1)
//        40..47  g blk0:     40 + kt*4 + nt                 (K=32, h part)
//        48..127 g blk1..5:  48 + (blk-1)*16 + kt*4 + nt    (K=64, kt 0..3)
__device__ uint32_t d_bfrag[128 * 64];

// ---------------- helpers ----------------
__device__ __forceinline__ uint32_t pack_f16x2(float lo, float hi) {
    uint32_t r;
    asm("cvt.rn.f16x2.f32 %0, %1, %2;" : "=r"(r) : "f"(hi), "f"(lo));
    return r;
}
#define MMA16816(d, a, b) \
    asm volatile("mma.sync.aligned.m16n8k16.row.col.f32.f16.f16.f32 " \
        "{%0,%1,%2,%3}, {%4,%5,%6,%7}, {%8,%9}, {%0,%1,%2,%3};" \
        : "+f"((d)[0]), "+f"((d)[1]), "+f"((d)[2]), "+f"((d)[3]) \
        : "r"((a)[0]), "r"((a)[1]), "r"((a)[2]), "r"((a)[3]), \
          "r"((b)[0]), "r"((b)[1]))

// chunk: load 4 B units (8 regs), run one A pass for both tiles
#define CHUNK1(ubase, A0, A1) do {                                               \
    uint32_t Bc[4][2];                                                           \
    _Pragma("unroll")                                                            \
    for (int nt = 0; nt < 4; nt++) {                                             \
        uint2 v = *(const uint2*)(s_bf + ((ubase) + nt) * 64 + lane * 2);        \
        Bc[nt][0] = v.x; Bc[nt][1] = v.y;                                        \
    }                                                                            \
    _Pragma("unroll")                                                            \
    for (int nt = 0; nt < 4; nt++) {                                             \
        MMA16816(acc[0][nt], (A0), Bc[nt]);                                      \
        MMA16816(acc[1][nt], (A1), Bc[nt]);                                      \
    }                                                                            \
} while (0)

// ---------------- precompute kernel (parallelized: 48 blocks) ----------------
// blocks 0..15  : per-batch fused biases (b = blockIdx.x)
// blocks 16..47 : B-fragment conversion (256 entries per block)
__global__ void precompute_kernel(
    const float* __restrict__ x_params, const float* __restrict__ t_params,
    const float* __restrict__ xW1, const float* __restrict__ xb1,
    const float* __restrict__ xW2, const float* __restrict__ xb2,
    const float* __restrict__ tW1, const float* __restrict__ tb1,
    const float* __restrict__ tW2, const float* __restrict__ tb2,
    const float* __restrict__ h0,  const float* __restrict__ gh0,
    const float* __restrict__ f_Wh, const float* __restrict__ f_bh,
    const float* __restrict__ f_Wz, const float* __restrict__ f_bz,
    const float* __restrict__ g_Wh, const float* __restrict__ g_bh,
    const float* __restrict__ g_Wz, const float* __restrict__ g_bz)
{
    const int t = threadIdx.x;  // 256 threads
    if (blockIdx.x < 16) {
        const int b = blockIdx.x;
        __shared__ float s1x[DIMK], s1t[DIMK], ex[DIMK], et[DIMK];
        if (t < DIMK) {
            float a = xb1[t];
            for (int p = 0; p < 16; p++) a += x_params[b * 16 + p] * xW1[p * DIMK + t];
            s1x[t] = sinf(a);
            float c = tb1[t];
            for (int p = 0; p < 8; p++) c += t_params[b * 8 + p] * tW1[p * DIMK + t];
            s1t[t] = sinf(c);
        }
        __syncthreads();
        if (t < DIMK) {
            float a = xb2[t], c = tb2[t];
            for (int m = 0; m < DIMK; m++) {
                a += s1x[m] * xW2[m * DIMK + t];
                c += s1t[m] * tW2[m * DIMK + t];
            }
            ex[t] = a;
            et[t] = c;
        }
        __syncthreads();
        if (t < NBLK * DIMK) {
            int blk = t >> 5, k = t & 31;
            float fa = f_bh[blk * DIMK + k] + f_bz[blk * DIMK + k];
            for (int m = 0; m < DIMK; m++)
                fa += et[m] * f_Wz[(blk * 34 + 2 + m) * DIMK + k];
            if (blk == 0)
                for (int m = 0; m < DIMK; m++)
                    fa += h0[m] * f_Wh[m * DIMK + k];
            d_fbias[(blk * NB + b) * DIMK + k] = fa;
            float ga = g_bh[blk * DIMK + k] + g_bz[blk * DIMK + k];
            for (int m = 0; m < DIMK; m++)
                ga += ex[m] * g_Wz[(blk * 64 + 32 + m) * DIMK + k];
            if (blk == 0)
                for (int m = 0; m < DIMK; m++)
                    ga += gh0[m] * g_Wh[m * DIMK + k];
            d_gbias[(blk * NB + b) * DIMK + k] = ga;
        }
    } else {
        // ---- B fragments (fp16 RN, per-lane mma layout) ----
        int e = (blockIdx.x - 16) * 256 + t;   // 32 * 256 = 8192 entries
        int u = e >> 6, r6 = e & 63, lane = r6 >> 1, reg = r6 & 1;
        int kt, nt, blk, isG;
        if (u < 40)      { blk = u / 8 + 1; int q = u % 8;  kt = q >> 2; nt = q & 3; isG = 0; }
        else if (u < 48) { int q = u - 40;  blk = 0;        kt = q >> 2; nt = q & 3; isG = 1; }
        else             { int q = u - 48;  blk = q / 16 + 1; q %= 16;   kt = q >> 2; nt = q & 3; isG = 1; }
        int k0 = kt * 16 + (lane & 3) * 2 + reg * 8;  // rows k0, k0+1
        int n  = nt * 8 + (lane >> 2);
        float w0, w1;
        if (!isG) {
            w0 = f_Wh[blk * 1024 + k0 * 32 + n];
            w1 = f_Wh[blk * 1024 + (k0 + 1) * 32 + n];
        } else if (blk == 0) {
            w0 = g_Wz[k0 * 32 + n];          // g blk0: h part rows 0..31
            w1 = g_Wz[(k0 + 1) * 32 + n];
        } else {
            w0 = (k0 < 32)     ? g_Wh[blk * 1024 + k0 * 32 + n]
                               : g_Wz[blk * 2048 + (k0 - 32) * 32 + n];
            int k1 = k0 + 1;
            w1 = (k1 < 32)     ? g_Wh[blk * 1024 + k1 * 32 + n]
                               : g_Wz[blk * 2048 + (k1 - 32) * 32 + n];
        }
        d_bfrag[e] = pack_f16x2(w0, w1);   // low half = smaller k
    }
}

// ---------------- smem layout ----------------
#define SM_BF_U32 (128 * 64)                      // 8192 u32 = 32 KB
#define SMEM_BYTES (32768 + (192 * 4 + 64) * 4)

// ---------- main kernel: 128 thr, tt=2 (B-sharing), 5 CTAs/SM, all-1-pass ----------
__global__ void __launch_bounds__(128, 5) main_kernel(
    const float* __restrict__ coords,  // (B,N,2)
    const float* __restrict__ f_Wz,    // (6,34,32)
    const float* __restrict__ d_W,     // (32)
    const float* __restrict__ d_b,     // (1)
    float* __restrict__ out)           // (B,N,N)
{
    extern __shared__ char smem[];
    uint32_t* s_bf  = (uint32_t*)smem;
    float*    s_fb  = (float*)(smem + 32768);
    float*    s_z0  = s_fb + 192;
    float*    s_z1  = s_z0 + 192;
    float*    s_gb  = s_z1 + 192;
    float*    s_dW  = s_gb + 192;   // 32

    const int tid  = threadIdx.x;
    const int w    = tid >> 5;
    const int lane = tid & 31;
    const int t4   = lane >> 2;
    const int m4   = lane & 3;
    // grid: [b(4b) | igrp(6b) | jgrp(1b)] = 2048 CTAs
    const int b    = blockIdx.x >> 7;
    const int igrp = (blockIdx.x >> 1) & 63;
    const int jgrp = blockIdx.x & 1;
    const int i0   = igrp * NITER;

    // ---- stage B fragments + per-batch vectors ----
    {
        const uint4* src = (const uint4*)d_bfrag;
        uint4* dst = (uint4*)s_bf;
        for (int idx = tid; idx < SM_BF_U32 / 4; idx += 128) dst[idx] = src[idx];
    }
    for (int idx = tid; idx < 192; idx += 128) {
        int blk = idx >> 5, k = idx & 31;
        s_fb[idx] = d_fbias[(blk * NB + b) * DIMK + k];
        s_gb[idx] = d_gbias[(blk * NB + b) * DIMK + k];
        s_z0[idx] = f_Wz[(blk * 34 + 0) * DIMK + k];
        s_z1[idx] = f_Wz[(blk * 34 + 1) * DIMK + k];
    }
    if (tid < 32) s_dW[tid] = d_W[tid];
    __syncthreads();

    const float dbv = d_b[0];

    // x for this warp's two tiles (j fixed across i)
    float xr[2][2];
#pragma unroll
    for (int tt = 0; tt < 2; tt++) {
        int j = jgrp * 128 + (w * 2 + tt) * 16 + t4;
        xr[tt][0] = coords[(b * NN + j) * 2 + 0];
        xr[tt][1] = coords[(b * NN + j + 8) * 2 + 0];
    }

    uint32_t ahi[2][8], hh[2][8];
    float acc[2][4][4];

#pragma unroll 1
    for (int ii = 0; ii < NITER; ii++) {
        const int i = i0 + ii;
        const float tc = coords[(b * NN + i) * 2 + 1];

        // ========== f blk0: h = sin(fb + tc*z1 + x*z0) ==========
#pragma unroll
        for (int tt = 0; tt < 2; tt++)
#pragma unroll
            for (int nt = 0; nt < 4; nt++) {
                int c = nt * 8 + m4 * 2;
                float2 fb2 = *(float2*)(s_fb + c);
                float2 z02 = *(float2*)(s_z0 + c);
                float2 z12 = *(float2*)(s_z1 + c);
                float bx = fmaf(tc, z12.x, fb2.x);
                float by = fmaf(tc, z12.y, fb2.y);
                float s0 = __sinf(fmaf(xr[tt][0], z02.x, bx));
                float s1 = __sinf(fmaf(xr[tt][0], z02.y, by));
                float s2 = __sinf(fmaf(xr[tt][1], z02.x, bx));
                float s3 = __sinf(fmaf(xr[tt][1], z02.y, by));
                int kt = nt >> 1, sl = (nt & 1) * 2;
                ahi[tt][kt * 4 + sl]     = pack_f16x2(s0, s1);
                ahi[tt][kt * 4 + sl + 1] = pack_f16x2(s2, s3);
            }

        // ========== f blks 1..5 (K=32, 1-pass) ==========
#pragma unroll 1
        for (int blk = 1; blk < NBLK; blk++) {
            const int ub = (blk - 1) * 8;
            const bool lastf = (blk == NBLK - 1);
#pragma unroll
            for (int tt = 0; tt < 2; tt++)
#pragma unroll
                for (int nt = 0; nt < 4; nt++) {
                    int c = blk * 32 + nt * 8 + m4 * 2;
                    float2 fb2 = *(float2*)(s_fb + c);
                    float2 z02 = *(float2*)(s_z0 + c);
                    float2 z12 = *(float2*)(s_z1 + c);
                    float bx = fmaf(tc, z12.x, fb2.x);
                    float by = fmaf(tc, z12.y, fb2.y);
                    acc[tt][nt][0] = fmaf(xr[tt][0], z02.x, bx);
                    acc[tt][nt][1] = fmaf(xr[tt][0], z02.y, by);
                    acc[tt][nt][2] = fmaf(xr[tt][1], z02.x, bx);
                    acc[tt][nt][3] = fmaf(xr[tt][1], z02.y, by);
                }
#pragma unroll
            for (int kt = 0; kt < 2; kt++)
                CHUNK1(ub + kt * 4, &ahi[0][kt * 4], &ahi[1][kt * 4]);
            // epilogue: sin + repack (f output h goes to hh)
#pragma unroll
            for (int tt = 0; tt < 2; tt++)
#pragma unroll
                for (int nt = 0; nt < 4; nt++) {
                    float s0 = __sinf(acc[tt][nt][0]);
                    float s1 = __sinf(acc[tt][nt][1]);
                    float s2 = __sinf(acc[tt][nt][2]);
                    float s3 = __sinf(acc[tt][nt][3]);
                    int kt = nt >> 1, sl = (nt & 1) * 2;
                    uint32_t p01 = pack_f16x2(s0, s1);
                    uint32_t p23 = pack_f16x2(s2, s3);
                    if (!lastf) {
                        ahi[tt][kt * 4 + sl]     = p01;
                        ahi[tt][kt * 4 + sl + 1] = p23;
                    } else {
                        hh[tt][kt * 4 + sl]     = p01;
                        hh[tt][kt * 4 + sl + 1] = p23;
                    }
                }
        }

        // ========== g blk0 (K=32, A = h) ==========
        {
#pragma unroll
            for (int tt = 0; tt < 2; tt++)
#pragma unroll
                for (int nt = 0; nt < 4; nt++) {
                    int c = nt * 8 + m4 * 2;
                    float2 gb2 = *(float2*)(s_gb + c);
                    acc[tt][nt][0] = gb2.x;
                    acc[tt][nt][1] = gb2.y;
                    acc[tt][nt][2] = gb2.x;
                    acc[tt][nt][3] = gb2.y;
                }
#pragma unroll
            for (int kt = 0; kt < 2; kt++)
                CHUNK1(40 + kt * 4, &hh[0][kt * 4], &hh[1][kt * 4]);
#pragma unroll
            for (int tt = 0; tt < 2; tt++)
#pragma unroll
                for (int nt = 0; nt < 4; nt++) {
                    float s0 = __sinf(acc[tt][nt][0]);
                    float s1 = __sinf(acc[tt][nt][1]);
                    float s2 = __sinf(acc[tt][nt][2]);
                    float s3 = __sinf(acc[tt][nt][3]);
                    int kt = nt >> 1, sl = (nt & 1) * 2;
                    ahi[tt][kt * 4 + sl]     = pack_f16x2(s0, s1);
                    ahi[tt][kt * 4 + sl + 1] = pack_f16x2(s2, s3);
                }
        }

        // ========== g blks 1..5 (K=64: A = [gh ; h], both 1-pass) ==========
        // ORDER: hh-part MMAs FIRST (independent of the just-computed sins),
        // giving the prev layer's sin->cvt->pack chain time to drain before
        // the ahi-dependent MMAs issue.
        float p0[2], p1[2];
#pragma unroll
        for (int tt = 0; tt < 2; tt++) { p0[tt] = 0.0f; p1[tt] = 0.0f; }

#pragma unroll 1
        for (int blk = 1; blk < NBLK; blk++) {
            const int ub = 48 + (blk - 1) * 16;
#pragma unroll
            for (int tt = 0; tt < 2; tt++)
#pragma unroll
                for (int nt = 0; nt < 4; nt++) {
                    int c = blk * 32 + nt * 8 + m4 * 2;
                    float2 gb2 = *(float2*)(s_gb + c);
                    acc[tt][nt][0] = gb2.x;
                    acc[tt][nt][1] = gb2.y;
                    acc[tt][nt][2] = gb2.x;
                    acc[tt][nt][3] = gb2.y;
                }
            // h part first (kt 2,3 at ub+8..): independent of prev-layer sins
#pragma unroll
            for (int kt = 0; kt < 2; kt++)
                CHUNK1(ub + 8 + kt * 4, &hh[0][kt * 4], &hh[1][kt * 4]);
            // gh part second (kt 0,1 at ub..): consumes ahi (prev-layer sins)
#pragma unroll
            for (int kt = 0; kt < 2; kt++)
                CHUNK1(ub + kt * 4, &ahi[0][kt * 4], &ahi[1][kt * 4]);

            const bool last = (blk == NBLK - 1);
#pragma unroll
            for (int tt = 0; tt < 2; tt++)
#pragma unroll
                for (int nt = 0; nt < 4; nt++) {
                    float s0 = __sinf(acc[tt][nt][0]);
                    float s1 = __sinf(acc[tt][nt][1]);
                    float s2 = __sinf(acc[tt][nt][2]);
                    float s3 = __sinf(acc[tt][nt][3]);
                    if (!last) {
                        int kt = nt >> 1, sl = (nt & 1) * 2;
                        ahi[tt][kt * 4 + sl]     = pack_f16x2(s0, s1);
                        ahi[tt][kt * 4 + sl + 1] = pack_f16x2(s2, s3);
                    } else {
                        int c = nt * 8 + m4 * 2;
                        float2 dw2 = *(float2*)(s_dW + c);
                        p0[tt] += s0 * dw2.x + s1 * dw2.y;
                        p1[tt] += s2 * dw2.x + s3 * dw2.y;
                    }
                }
        }

        // ========== decode reduce + store ==========
#pragma unroll
        for (int tt = 0; tt < 2; tt++) {
            p0[tt] += __shfl_xor_sync(0xffffffffu, p0[tt], 1);
            p0[tt] += __shfl_xor_sync(0xffffffffu, p0[tt], 2);
            p1[tt] += __shfl_xor_sync(0xffffffffu, p1[tt], 1);
            p1[tt] += __shfl_xor_sync(0xffffffffu, p1[tt], 2);
            if (m4 == 0) {
                int r0 = jgrp * 128 + (w * 2 + tt) * 16 + t4;
                out[b * (NN * NN) + i * NN + r0]     = p0[tt] + dbv;
                out[b * (NN * NN) + i * NN + r0 + 8] = p1[tt] + dbv;
            }
        }
    }
}

// ---------------- launch ----------------
extern "C" void kernel_launch(void* const* d_in, const int* in_sizes, int n_in,
                              void* d_out, int out_size) {
    const float* coords   = (const float*)d_in[0];
    const float* x_params = (const float*)d_in[1];
    const float* t_params = (const float*)d_in[2];
    const float* xW1 = (const float*)d_in[3];
    const float* xb1 = (const float*)d_in[4];
    const float* xW2 = (const float*)d_in[5];
    const float* xb2 = (const float*)d_in[6];
    const float* tW1 = (const float*)d_in[7];
    const float* tb1 = (const float*)d_in[8];
    const float* tW2 = (const float*)d_in[9];
    const float* tb2 = (const float*)d_in[10];
    const float* h0  = (const float*)d_in[11];
    const float* gh0 = (const float*)d_in[12];
    const float* f_Wh = (const float*)d_in[13];
    const float* f_bh = (const float*)d_in[14];
    const float* f_Wz = (const float*)d_in[15];
    const float* f_bz = (const float*)d_in[16];
    const float* g_Wh = (const float*)d_in[17];
    const float* g_bh = (const float*)d_in[18];
    const float* g_Wz = (const float*)d_in[19];
    const float* g_bz = (const float*)d_in[20];
    const float* d_W  = (const float*)d_in[21];
    const float* d_b  = (const float*)d_in[22];
    float* out = (float*)d_out;

    precompute_kernel<<<48, 256>>>(x_params, t_params, xW1, xb1, xW2, xb2,
                                   tW1, tb1, tW2, tb2, h0, gh0,
                                   f_Wh, f_bh, f_Wz, f_bz,
                                   g_Wh, g_bh, g_Wz, g_bz);

    cudaFuncSetAttribute(main_kernel, cudaFuncAttributeMaxDynamicSharedMemorySize,
                         SMEM_BYTES);
    // grid: [b(4b) | igrp(6b) | jgrp(1b)] = 16 * 64 * 2 = 2048 CTAs
    main_kernel<<<NB * (NN / NITER) * 2, 128, SMEM_BYTES>>>(coords, f_Wz, d_W, d_b, out);
}

// round 15
// speedup vs baseline: 1.2769x; 1.0258x over previous
#include <cuda_runtime.h>
#include <cuda_bf16.h>
#include <cstdint>

#define DIMK 32
#define NBLK 6
#define NB   16
#define NN   256
#define NITEMS (NB * NN * 2)   // 8192 work items: (b, i, jgrp)

// ---------------- global scratch ----------------
__device__ float    d_fbias[NBLK * NB * DIMK];
__device__ float    d_gbias[NBLK * NB * DIMK];
__device__ unsigned int d_work;   // dynamic work counter (reset each launch)
// B fragments (fp16, round-to-nearest) in exact mma.sync per-lane layout:
// units: 0..39   f blk1..5:  (blk-1)*8 + kt*4 + nt          (K=32, kt 0..1)
//        40..47  g blk0:     40 + kt*4 + nt                 (K=32, h part)
//        48..127 g blk1..5:  48 + (blk-1)*16 + kt*4 + nt    (K=64, kt 0..3)
__device__ uint32_t d_bfrag[128 * 64];

// ---------------- helpers ----------------
__device__ __forceinline__ uint32_t pack_f16x2(float lo, float hi) {
    uint32_t r;
    asm("cvt.rn.f16x2.f32 %0, %1, %2;" : "=r"(r) : "f"(hi), "f"(lo));
    return r;
}
#define MMA16816(d, a, b) \
    asm volatile("mma.sync.aligned.m16n8k16.row.col.f32.f16.f16.f32 " \
        "{%0,%1,%2,%3}, {%4,%5,%6,%7}, {%8,%9}, {%0,%1,%2,%3};" \
        : "+f"((d)[0]), "+f"((d)[1]), "+f"((d)[2]), "+f"((d)[3]) \
        : "r"((a)[0]), "r"((a)[1]), "r"((a)[2]), "r"((a)[3]), \
          "r"((b)[0]), "r"((b)[1]))

// chunk: load 4 B units (8 regs), run one A pass for both tiles
#define CHUNK1(ubase, A0, A1) do {                                               \
    uint32_t Bc[4][2];                                                           \
    _Pragma("unroll")                                                            \
    for (int nt = 0; nt < 4; nt++) {                                             \
        uint2 v = *(const uint2*)(s_bf + ((ubase) + nt) * 64 + lane * 2);        \
        Bc[nt][0] = v.x; Bc[nt][1] = v.y;                                        \
    }                                                                            \
    _Pragma("unroll")                                                            \
    for (int nt = 0; nt < 4; nt++) {                                             \
        MMA16816(acc[0][nt], (A0), Bc[nt]);                                      \
        MMA16816(acc[1][nt], (A1), Bc[nt]);                                      \
    }                                                                            \
} while (0)

// ---------------- precompute kernel (parallelized: 48 blocks) ----------------
// blocks 0..15  : per-batch fused biases (b = blockIdx.x)
// blocks 16..47 : B-fragment conversion (256 entries per block)
__global__ void precompute_kernel(
    const float* __restrict__ x_params, const float* __restrict__ t_params,
    const float* __restrict__ xW1, const float* __restrict__ xb1,
    const float* __restrict__ xW2, const float* __restrict__ xb2,
    const float* __restrict__ tW1, const float* __restrict__ tb1,
    const float* __restrict__ tW2, const float* __restrict__ tb2,
    const float* __restrict__ h0,  const float* __restrict__ gh0,
    const float* __restrict__ f_Wh, const float* __restrict__ f_bh,
    const float* __restrict__ f_Wz, const float* __restrict__ f_bz,
    const float* __restrict__ g_Wh, const float* __restrict__ g_bh,
    const float* __restrict__ g_Wz, const float* __restrict__ g_bz)
{
    const int t = threadIdx.x;  // 256 threads
    if (blockIdx.x == 0 && t == 0) d_work = 0u;   // reset work counter each launch
    if (blockIdx.x < 16) {
        const int b = blockIdx.x;
        __shared__ float s1x[DIMK], s1t[DIMK], ex[DIMK], et[DIMK];
        if (t < DIMK) {
            float a = xb1[t];
            for (int p = 0; p < 16; p++) a += x_params[b * 16 + p] * xW1[p * DIMK + t];
            s1x[t] = sinf(a);
            float c = tb1[t];
            for (int p = 0; p < 8; p++) c += t_params[b * 8 + p] * tW1[p * DIMK + t];
            s1t[t] = sinf(c);
        }
        __syncthreads();
        if (t < DIMK) {
            float a = xb2[t], c = tb2[t];
            for (int m = 0; m < DIMK; m++) {
                a += s1x[m] * xW2[m * DIMK + t];
                c += s1t[m] * tW2[m * DIMK + t];
            }
            ex[t] = a;
            et[t] = c;
        }
        __syncthreads();
        if (t < NBLK * DIMK) {
            int blk = t >> 5, k = t & 31;
            float fa = f_bh[blk * DIMK + k] + f_bz[blk * DIMK + k];
            for (int m = 0; m < DIMK; m++)
                fa += et[m] * f_Wz[(blk * 34 + 2 + m) * DIMK + k];
            if (blk == 0)
                for (int m = 0; m < DIMK; m++)
                    fa += h0[m] * f_Wh[m * DIMK + k];
            d_fbias[(blk * NB + b) * DIMK + k] = fa;
            float ga = g_bh[blk * DIMK + k] + g_bz[blk * DIMK + k];
            for (int m = 0; m < DIMK; m++)
                ga += ex[m] * g_Wz[(blk * 64 + 32 + m) * DIMK + k];
            if (blk == 0)
                for (int m = 0; m < DIMK; m++)
                    ga += gh0[m] * g_Wh[m * DIMK + k];
            d_gbias[(blk * NB + b) * DIMK + k] = ga;
        }
    } else {
        // ---- B fragments (fp16 RN, per-lane mma layout) ----
        int e = (blockIdx.x - 16) * 256 + t;   // 32 * 256 = 8192 entries
        int u = e >> 6, r6 = e & 63, lane = r6 >> 1, reg = r6 & 1;
        int kt, nt, blk, isG;
        if (u < 40)      { blk = u / 8 + 1; int q = u % 8;  kt = q >> 2; nt = q & 3; isG = 0; }
        else if (u < 48) { int q = u - 40;  blk = 0;        kt = q >> 2; nt = q & 3; isG = 1; }
        else             { int q = u - 48;  blk = q / 16 + 1; q %= 16;   kt = q >> 2; nt = q & 3; isG = 1; }
        int k0 = kt * 16 + (lane & 3) * 2 + reg * 8;  // rows k0, k0+1
        int n  = nt * 8 + (lane >> 2);
        float w0, w1;
        if (!isG) {
            w0 = f_Wh[blk * 1024 + k0 * 32 + n];
            w1 = f_Wh[blk * 1024 + (k0 + 1) * 32 + n];
        } else if (blk == 0) {
            w0 = g_Wz[k0 * 32 + n];          // g blk0: h part rows 0..31
            w1 = g_Wz[(k0 + 1) * 32 + n];
        } else {
            w0 = (k0 < 32)     ? g_Wh[blk * 1024 + k0 * 32 + n]
                               : g_Wz[blk * 2048 + (k0 - 32) * 32 + n];
            int k1 = k0 + 1;
            w1 = (k1 < 32)     ? g_Wh[blk * 1024 + k1 * 32 + n]
                               : g_Wz[blk * 2048 + (k1 - 32) * 32 + n];
        }
        d_bfrag[e] = pack_f16x2(w0, w1);   // low half = smaller k
    }
}

// ---------------- smem layout ----------------
#define SM_BF_U32 (128 * 64)                      // 8192 u32 = 32 KB
#define SMEM_BYTES (32768 + (192 * 4 + 64) * 4)

// ---- persistent main kernel: 740 CTAs (148 SM x 5), dynamic work-stealing ----
__global__ void __launch_bounds__(128, 5) main_kernel(
    const float* __restrict__ coords,  // (B,N,2)
    const float* __restrict__ f_Wz,    // (6,34,32)
    const float* __restrict__ d_W,     // (32)
    const float* __restrict__ d_b,     // (1)
    float* __restrict__ out)           // (B,N,N)
{
    extern __shared__ char smem[];
    uint32_t* s_bf  = (uint32_t*)smem;
    float*    s_fb  = (float*)(smem + 32768);
    float*    s_z0  = s_fb + 192;
    float*    s_z1  = s_z0 + 192;
    float*    s_gb  = s_z1 + 192;
    float*    s_dW  = s_gb + 192;                 // 32 floats
    unsigned int* s_item = (unsigned int*)(s_dW + 32);

    const int tid  = threadIdx.x;
    const int w    = tid >> 5;
    const int lane = tid & 31;
    const int t4   = lane >> 2;
    const int m4   = lane & 3;

    // ---- one-time staging: B fragments + b-independent vectors ----
    {
        const uint4* src = (const uint4*)d_bfrag;
        uint4* dst = (uint4*)s_bf;
        for (int idx = tid; idx < SM_BF_U32 / 4; idx += 128) dst[idx] = src[idx];
    }
    for (int idx = tid; idx < 192; idx += 128) {
        int blk = idx >> 5, k = idx & 31;
        s_z0[idx] = f_Wz[(blk * 34 + 0) * DIMK + k];
        s_z1[idx] = f_Wz[(blk * 34 + 1) * DIMK + k];
    }
    if (tid < 32) s_dW[tid] = d_W[tid];

    const float dbv = d_b[0];

    uint32_t ahi[2][8], hh[2][8];
    float acc[2][4][4];

    // ---- persistent work loop ----
    for (;;) {
        // grab next item; barrier doubles as "all warps done with prev item's smem"
        if (tid == 0) *s_item = atomicAdd(&d_work, 1u);
        __syncthreads();
        const unsigned int item = *s_item;
        if (item >= NITEMS) break;
        const int b    = (int)(item >> 9);       // 512 items per batch
        const int i    = (int)((item >> 1) & 255);
        const int jgrp = (int)(item & 1);

        // stage per-batch biases for this item
        for (int idx = tid; idx < 192; idx += 128) {
            int blk = idx >> 5, k = idx & 31;
            s_fb[idx] = d_fbias[(blk * NB + b) * DIMK + k];
            s_gb[idx] = d_gbias[(blk * NB + b) * DIMK + k];
        }
        __syncthreads();

        // x for this warp's two tiles
        float xr[2][2];
#pragma unroll
        for (int tt = 0; tt < 2; tt++) {
            int j = jgrp * 128 + (w * 2 + tt) * 16 + t4;
            xr[tt][0] = coords[(b * NN + j) * 2 + 0];
            xr[tt][1] = coords[(b * NN + j + 8) * 2 + 0];
        }
        const float tc = coords[(b * NN + i) * 2 + 1];

        // ========== f blk0: h = sin(fb + tc*z1 + x*z0) ==========
#pragma unroll
        for (int tt = 0; tt < 2; tt++)
#pragma unroll
            for (int nt = 0; nt < 4; nt++) {
                int c = nt * 8 + m4 * 2;
                float2 fb2 = *(float2*)(s_fb + c);
                float2 z02 = *(float2*)(s_z0 + c);
                float2 z12 = *(float2*)(s_z1 + c);
                float bx = fmaf(tc, z12.x, fb2.x);
                float by = fmaf(tc, z12.y, fb2.y);
                float s0 = __sinf(fmaf(xr[tt][0], z02.x, bx));
                float s1 = __sinf(fmaf(xr[tt][0], z02.y, by));
                float s2 = __sinf(fmaf(xr[tt][1], z02.x, bx));
                float s3 = __sinf(fmaf(xr[tt][1], z02.y, by));
                int kt = nt >> 1, sl = (nt & 1) * 2;
                ahi[tt][kt * 4 + sl]     = pack_f16x2(s0, s1);
                ahi[tt][kt * 4 + sl + 1] = pack_f16x2(s2, s3);
            }

        // ========== f blks 1..5 (K=32, 1-pass) ==========
#pragma unroll 1
        for (int blk = 1; blk < NBLK; blk++) {
            const int ub = (blk - 1) * 8;
            const bool lastf = (blk == NBLK - 1);
#pragma unroll
            for (int tt = 0; tt < 2; tt++)
#pragma unroll
                for (int nt = 0; nt < 4; nt++) {
                    int c = blk * 32 + nt * 8 + m4 * 2;
                    float2 fb2 = *(float2*)(s_fb + c);
                    float2 z02 = *(float2*)(s_z0 + c);
                    float2 z12 = *(float2*)(s_z1 + c);
                    float bx = fmaf(tc, z12.x, fb2.x);
                    float by = fmaf(tc, z12.y, fb2.y);
                    acc[tt][nt][0] = fmaf(xr[tt][0], z02.x, bx);
                    acc[tt][nt][1] = fmaf(xr[tt][0], z02.y, by);
                    acc[tt][nt][2] = fmaf(xr[tt][1], z02.x, bx);
                    acc[tt][nt][3] = fmaf(xr[tt][1], z02.y, by);
                }
#pragma unroll
            for (int kt = 0; kt < 2; kt++)
                CHUNK1(ub + kt * 4, &ahi[0][kt * 4], &ahi[1][kt * 4]);
            // epilogue: sin + repack (f output h goes to hh)
#pragma unroll
            for (int tt = 0; tt < 2; tt++)
#pragma unroll
                for (int nt = 0; nt < 4; nt++) {
                    float s0 = __sinf(acc[tt][nt][0]);
                    float s1 = __sinf(acc[tt][nt][1]);
                    float s2 = __sinf(acc[tt][nt][2]);
                    float s3 = __sinf(acc[tt][nt][3]);
                    int kt = nt >> 1, sl = (nt & 1) * 2;
                    uint32_t p01 = pack_f16x2(s0, s1);
                    uint32_t p23 = pack_f16x2(s2, s3);
                    if (!lastf) {
                        ahi[tt][kt * 4 + sl]     = p01;
                        ahi[tt][kt * 4 + sl + 1] = p23;
                    } else {
                        hh[tt][kt * 4 + sl]     = p01;
                        hh[tt][kt * 4 + sl + 1] = p23;
                    }
                }
        }

        // ========== g blk0 (K=32, A = h) ==========
        {
#pragma unroll
            for (int tt = 0; tt < 2; tt++)
#pragma unroll
                for (int nt = 0; nt < 4; nt++) {
                    int c = nt * 8 + m4 * 2;
                    float2 gb2 = *(float2*)(s_gb + c);
                    acc[tt][nt][0] = gb2.x;
                    acc[tt][nt][1] = gb2.y;
                    acc[tt][nt][2] = gb2.x;
                    acc[tt][nt][3] = gb2.y;
                }
#pragma unroll
            for (int kt = 0; kt < 2; kt++)
                CHUNK1(40 + kt * 4, &hh[0][kt * 4], &hh[1][kt * 4]);
#pragma unroll
            for (int tt = 0; tt < 2; tt++)
#pragma unroll
                for (int nt = 0; nt < 4; nt++) {
                    float s0 = __sinf(acc[tt][nt][0]);
                    float s1 = __sinf(acc[tt][nt][1]);
                    float s2 = __sinf(acc[tt][nt][2]);
                    float s3 = __sinf(acc[tt][nt][3]);
                    int kt = nt >> 1, sl = (nt & 1) * 2;
                    ahi[tt][kt * 4 + sl]     = pack_f16x2(s0, s1);
                    ahi[tt][kt * 4 + sl + 1] = pack_f16x2(s2, s3);
                }
        }

        // ========== g blks 1..5 (K=64: A = [gh ; h], both 1-pass) ==========
        float p0[2], p1[2];
#pragma unroll
        for (int tt = 0; tt < 2; tt++) { p0[tt] = 0.0f; p1[tt] = 0.0f; }

#pragma unroll 1
        for (int blk = 1; blk < NBLK; blk++) {
            const int ub = 48 + (blk - 1) * 16;
#pragma unroll
            for (int tt = 0; tt < 2; tt++)
#pragma unroll
                for (int nt = 0; nt < 4; nt++) {
                    int c = blk * 32 + nt * 8 + m4 * 2;
                    float2 gb2 = *(float2*)(s_gb + c);
                    acc[tt][nt][0] = gb2.x;
                    acc[tt][nt][1] = gb2.y;
                    acc[tt][nt][2] = gb2.x;
                    acc[tt][nt][3] = gb2.y;
                }
            // h part first (independent of prev-layer sins), then gh part
#pragma unroll
            for (int kt = 0; kt < 2; kt++)
                CHUNK1(ub + 8 + kt * 4, &hh[0][kt * 4], &hh[1][kt * 4]);
#pragma unroll
            for (int kt = 0; kt < 2; kt++)
                CHUNK1(ub + kt * 4, &ahi[0][kt * 4], &ahi[1][kt * 4]);

            const bool last = (blk == NBLK - 1);
#pragma unroll
            for (int tt = 0; tt < 2; tt++)
#pragma unroll
                for (int nt = 0; nt < 4; nt++) {
                    float s0 = __sinf(acc[tt][nt][0]);
                    float s1 = __sinf(acc[tt][nt][1]);
                    float s2 = __sinf(acc[tt][nt][2]);
                    float s3 = __sinf(acc[tt][nt][3]);
                    if (!last) {
                        int kt = nt >> 1, sl = (nt & 1) * 2;
                        ahi[tt][kt * 4 + sl]     = pack_f16x2(s0, s1);
                        ahi[tt][kt * 4 + sl + 1] = pack_f16x2(s2, s3);
                    } else {
                        int c = nt * 8 + m4 * 2;
                        float2 dw2 = *(float2*)(s_dW + c);
                        p0[tt] += s0 * dw2.x + s1 * dw2.y;
                        p1[tt] += s2 * dw2.x + s3 * dw2.y;
                    }
                }
        }

        // ========== decode reduce + store ==========
#pragma unroll
        for (int tt = 0; tt < 2; tt++) {
            p0[tt] += __shfl_xor_sync(0xffffffffu, p0[tt], 1);
            p0[tt] += __shfl_xor_sync(0xffffffffu, p0[tt], 2);
            p1[tt] += __shfl_xor_sync(0xffffffffu, p1[tt], 1);
            p1[tt] += __shfl_xor_sync(0xffffffffu, p1[tt], 2);
            if (m4 == 0) {
                int r0 = jgrp * 128 + (w * 2 + tt) * 16 + t4;
                out[b * (NN * NN) + i * NN + r0]     = p0[tt] + dbv;
                out[b * (NN * NN) + i * NN + r0 + 8] = p1[tt] + dbv;
            }
        }
    }
}

// ---------------- launch ----------------
extern "C" void kernel_launch(void* const* d_in, const int* in_sizes, int n_in,
                              void* d_out, int out_size) {
    const float* coords   = (const float*)d_in[0];
    const float* x_params = (const float*)d_in[1];
    const float* t_params = (const float*)d_in[2];
    const float* xW1 = (const float*)d_in[3];
    const float* xb1 = (const float*)d_in[4];
    const float* xW2 = (const float*)d_in[5];
    const float* xb2 = (const float*)d_in[6];
    const float* tW1 = (const float*)d_in[7];
    const float* tb1 = (const float*)d_in[8];
    const float* tW2 = (const float*)d_in[9];
    const float* tb2 = (const float*)d_in[10];
    const float* h0  = (const float*)d_in[11];
    const float* gh0 = (const float*)d_in[12];
    const float* f_Wh = (const float*)d_in[13];
    const float* f_bh = (const float*)d_in[14];
    const float* f_Wz = (const float*)d_in[15];
    const float* f_bz = (const float*)d_in[16];
    const float* g_Wh = (const float*)d_in[17];
    const float* g_bh = (const float*)d_in[18];
    const float* g_Wz = (const float*)d_in[19];
    const float* g_bz = (const float*)d_in[20];
    const float* d_W  = (const float*)d_in[21];
    const float* d_b  = (const float*)d_in[22];
    float* out = (float*)d_out;

    precompute_kernel<<<48, 256>>>(x_params, t_params, xW1, xb1, xW2, xb2,
                                   tW1, tb1, tW2, tb2, h0, gh0,
                                   f_Wh, f_bh, f_Wz, f_bz,
                                   g_Wh, g_bh, g_Wz, g_bz);

    cudaFuncSetAttribute(main_kernel, cudaFuncAttributeMaxDynamicSharedMemorySize,
                         SMEM_BYTES);
    // persistent grid: exactly one full wave (148 SMs x 5 CTAs)
    main_kernel<<<148 * 5, 128, SMEM_BYTES>>>(coords, f_Wz, d_W, d_b, out);
}